// round 10
// baseline (speedup 1.0000x reference)
#include <cuda_runtime.h>
#include <cuda_fp16.h>

#define NG 32
#define NN 2048
#define NT 65536           // NG*NN
#define NE 1048576
#define NHEADS 8
#define F 12               // GAT_OUT
#define FH 96              // NHEADS*F
#define OUTC 9
#define KS 8               // K-slices for xproj split-K
#define SLICE 256          // n per slice (KS*SLICE = NN)

#define PDL_TRIGGER() asm volatile("griddepcontrol.launch_dependents;")
#define PDL_WAIT()    asm volatile("griddepcontrol.wait;" ::: "memory")

// ---------------- scratch (static device memory only) ----------------
__device__ __align__(16) uint4 g_rec[NT * NHEADS * 2];   // {asrc f32 | 12 x f16 | pad} per (n,h)
__device__ float g_adst[NT * NHEADS];
__device__ int   g_deg[NT];            // BSS-zero; re-zeroed by k_scan3 each run
__device__ int   g_off[NT + 1];
__device__ int   g_cur[NT];
__device__ int   g_bsum[64];
__device__ int   g_csr[NE];
__device__ __align__(16) float g_post[F * NT];             // channel-major [t][gn]
__device__ __align__(16) float g_wT1[NN * 128];            // w_ih1^T [n][j]
__device__ __align__(16) float g_part[F * KS * NG * 128];  // split-K partials [t][ks][b][j]
__device__ __align__(16) float g_hs2[F * NG * 128];

__device__ __forceinline__ float lrelu(float v) { return v > 0.f ? v : 0.2f * v; }
__device__ __forceinline__ float sigf(float v) { return 1.0f / (1.0f + __expf(-v)); }

// ---- prep: xp = x@W + logits, pack records, edge histogram ----
__global__ void k_prep(const float* __restrict__ x, const float* __restrict__ W,
                       const float* __restrict__ av_s, const float* __restrict__ av_d,
                       const int* __restrict__ ei) {
    PDL_TRIGGER();
    __shared__ float Ws[F * FH];
    __shared__ float as_s[FH], ad_s[FH];
    for (int i = threadIdx.x; i < F * FH; i += blockDim.x) Ws[i] = W[i];
    for (int i = threadIdx.x; i < FH; i += blockDim.x) { as_s[i] = av_s[i]; ad_s[i] = av_d[i]; }
    __syncthreads();

    int gid = blockIdx.x * blockDim.x + threadIdx.x;   // 0 .. 524287 = n*8+h

    atomicAdd(&g_deg[ei[NE + gid]], 1);
    atomicAdd(&g_deg[ei[NE + gid + NT * NHEADS]], 1);

    int n = gid >> 3, h = gid & 7;
    const float4* xv = reinterpret_cast<const float4*>(x + n * F);
    float4 v0 = xv[0], v1 = xv[1], v2 = xv[2];
    float xr[F] = {v0.x, v0.y, v0.z, v0.w, v1.x, v1.y, v1.z, v1.w, v2.x, v2.y, v2.z, v2.w};

    float o[F];
    float sa = 0.f, sd = 0.f;
#pragma unroll
    for (int c = 0; c < F; c++) {
        float s = 0.f;
#pragma unroll
        for (int k = 0; k < F; k++) s += xr[k] * Ws[k * FH + h * F + c];
        o[c] = s;
        sa += s * as_s[h * F + c];
        sd += s * ad_s[h * F + c];
    }
    uint4 r0, r1;
    r0.x = __float_as_uint(sa);
    __half2 p;
    p = __floats2half2_rn(o[0], o[1]);   r0.y = *reinterpret_cast<unsigned*>(&p);
    p = __floats2half2_rn(o[2], o[3]);   r0.z = *reinterpret_cast<unsigned*>(&p);
    p = __floats2half2_rn(o[4], o[5]);   r0.w = *reinterpret_cast<unsigned*>(&p);
    p = __floats2half2_rn(o[6], o[7]);   r1.x = *reinterpret_cast<unsigned*>(&p);
    p = __floats2half2_rn(o[8], o[9]);   r1.y = *reinterpret_cast<unsigned*>(&p);
    p = __floats2half2_rn(o[10], o[11]); r1.z = *reinterpret_cast<unsigned*>(&p);
    r1.w = 0u;
    g_rec[gid * 2]     = r0;
    g_rec[gid * 2 + 1] = r1;
    g_adst[gid] = sd;
}

// ---- scan1: (prologue) tiled transpose of w_ih1, then block-local degree scan ----
__global__ void __launch_bounds__(1024) k_scan1(const float* __restrict__ w1) {
    PDL_TRIGGER();
    __shared__ float ts[32][33];
    int tid = threadIdx.x;
    int r = tid >> 5, c = tid & 31;
    // transpose 128x2048 -> 2048x128 in 32x32 tiles; 256 tiles, 4 per block
#pragma unroll
    for (int q = 0; q < 4; q++) {
        int t = blockIdx.x * 4 + q;
        int j0 = (t >> 6) * 32, n0 = (t & 63) * 32;
        ts[r][c] = w1[(j0 + r) * NN + n0 + c];
        __syncthreads();
        g_wT1[(n0 + r) * 128 + j0 + c] = ts[c][r];
        __syncthreads();
    }

    PDL_WAIT();   // g_deg ready (prep done)

    int g = blockIdx.x * 1024 + tid;
    int lane = tid & 31, wid = tid >> 5;
    int v = g_deg[g];
    int incl = v;
#pragma unroll
    for (int off = 1; off < 32; off <<= 1) {
        int t = __shfl_up_sync(0xffffffffu, incl, off);
        if (lane >= off) incl += t;
    }
    __shared__ int wsum[32];
    if (lane == 31) wsum[wid] = incl;
    __syncthreads();
    if (wid == 0) {
        int s = wsum[lane];
        int si = s;
#pragma unroll
        for (int off = 1; off < 32; off <<= 1) {
            int t = __shfl_up_sync(0xffffffffu, si, off);
            if (lane >= off) si += t;
        }
        wsum[lane] = si - s;
    }
    __syncthreads();
    incl += wsum[wid];
    g_off[g] = incl - v;
    if (tid == 1023) g_bsum[blockIdx.x] = incl;
}

__global__ void k_scan3() {
    PDL_TRIGGER();
    PDL_WAIT();
    __shared__ int tmp[64];
    __shared__ int pre;
    int tid = threadIdx.x;
    if (tid < 64) tmp[tid] = g_bsum[tid];
    __syncthreads();
    if (tid == 0) {
        int s = 0;
        int nb = blockIdx.x;
        for (int i = 0; i < nb; i++) s += tmp[i];
        pre = s;
    }
    __syncthreads();
    int g = blockIdx.x * 1024 + tid;
    int o = g_off[g] + pre;
    g_off[g] = o;
    g_cur[g] = o;
    g_deg[g] = 0;
    if (g == 0) g_off[NT] = NE;
}

// ---- scatter: 4 edges per thread (MLP=4), edge loads overlap scan3 via PDL ----
__global__ void k_scatter(const int* __restrict__ ei) {
    PDL_TRIGGER();
    int g = blockIdx.x * blockDim.x + threadIdx.x;   // 262144 threads
    int4 d4 = *reinterpret_cast<const int4*>(ei + NE + g * 4);
    int4 s4 = *reinterpret_cast<const int4*>(ei + g * 4);
    PDL_WAIT();   // g_cur ready
    int p0 = atomicAdd(&g_cur[d4.x], 1);
    int p1 = atomicAdd(&g_cur[d4.y], 1);
    int p2 = atomicAdd(&g_cur[d4.z], 1);
    int p3 = atomicAdd(&g_cur[d4.w], 1);
    g_csr[p0] = s4.x;
    g_csr[p1] = s4.y;
    g_csr[p2] = s4.z;
    g_csr[p3] = s4.w;
}

// ---- GAT aggregation: thread-per-(n,h), 4-edge batches ----
__global__ void __launch_bounds__(256) k_gat(
        const float* __restrict__ bias, const float* __restrict__ gamma,
        const float* __restrict__ beta, const float* __restrict__ mean,
        const float* __restrict__ var) {
    PDL_TRIGGER();
    __shared__ float sb[F], sg[F], sbe[F], smn[F], svr[F];
    if (threadIdx.x < F) {
        sb[threadIdx.x]  = bias[threadIdx.x];
        sg[threadIdx.x]  = gamma[threadIdx.x];
        sbe[threadIdx.x] = beta[threadIdx.x];
        smn[threadIdx.x] = mean[threadIdx.x];
        svr[threadIdx.x] = var[threadIdx.x];
    }
    __syncthreads();
    PDL_WAIT();   // csr/off (and rec/adst transitively) ready

    int gid = blockIdx.x * blockDim.x + threadIdx.x;   // n*8 + h
    int n = gid >> 3, h = gid & 7;
    float adn = g_adst[gid];
    int st = g_off[n], en = g_off[n + 1];

    float denom = 0.f;
    float acc[F];
#pragma unroll
    for (int c = 0; c < F; c++) acc[c] = 0.f;

#define ACC2(r0, r1)                                                           \
    {                                                                          \
        float w = __expf(lrelu(__uint_as_float(r0.x) + adn));                  \
        denom += w;                                                            \
        __half2 hp; float2 f2;                                                 \
        hp = *reinterpret_cast<__half2*>(&r0.y); f2 = __half22float2(hp);      \
        acc[0] += w * f2.x; acc[1] += w * f2.y;                                \
        hp = *reinterpret_cast<__half2*>(&r0.z); f2 = __half22float2(hp);      \
        acc[2] += w * f2.x; acc[3] += w * f2.y;                                \
        hp = *reinterpret_cast<__half2*>(&r0.w); f2 = __half22float2(hp);      \
        acc[4] += w * f2.x; acc[5] += w * f2.y;                                \
        hp = *reinterpret_cast<__half2*>(&r1.x); f2 = __half22float2(hp);      \
        acc[6] += w * f2.x; acc[7] += w * f2.y;                                \
        hp = *reinterpret_cast<__half2*>(&r1.y); f2 = __half22float2(hp);      \
        acc[8] += w * f2.x; acc[9] += w * f2.y;                                \
        hp = *reinterpret_cast<__half2*>(&r1.z); f2 = __half22float2(hp);      \
        acc[10] += w * f2.x; acc[11] += w * f2.y;                              \
    }

    {
        uint4 a0 = g_rec[(unsigned)gid * 2u], a1 = g_rec[(unsigned)gid * 2u + 1u];
        ACC2(a0, a1);
    }
    int i = st;
    for (; i + 4 <= en; i += 4) {
        int s0 = g_csr[i], s1 = g_csr[i + 1], s2 = g_csr[i + 2], s3 = g_csr[i + 3];
        const uint4* p0 = &g_rec[(unsigned)(s0 * NHEADS + h) * 2u];
        const uint4* p1 = &g_rec[(unsigned)(s1 * NHEADS + h) * 2u];
        const uint4* p2 = &g_rec[(unsigned)(s2 * NHEADS + h) * 2u];
        const uint4* p3 = &g_rec[(unsigned)(s3 * NHEADS + h) * 2u];
        uint4 a0 = p0[0], a1 = p0[1];
        uint4 b0 = p1[0], b1 = p1[1];
        uint4 c0 = p2[0], c1 = p2[1];
        uint4 d0 = p3[0], d1 = p3[1];
        ACC2(a0, a1); ACC2(b0, b1); ACC2(c0, c1); ACC2(d0, d1);
    }
    for (; i < en; i++) {
        int s = g_csr[i];
        const uint4* rp = &g_rec[(unsigned)(s * NHEADS + h) * 2u];
        uint4 a0 = rp[0], a1 = rp[1];
        ACC2(a0, a1);
    }
#undef ACC2

    float inv = 1.f / (denom + 1e-16f);
#pragma unroll
    for (int c = 0; c < F; c++) acc[c] *= inv;

#pragma unroll
    for (int s = 4; s > 0; s >>= 1)
#pragma unroll
        for (int c = 0; c < F; c++) acc[c] += __shfl_xor_sync(0xffffffffu, acc[c], s);

    if (h == 0) {
        float v[F];
#pragma unroll
        for (int c = 0; c < F; c++) {
            float t = acc[c] * 0.125f + sb[c];
            v[c] = (t - smn[c]) * rsqrtf(svr[c] + 1e-5f) * sg[c] + sbe[c];
        }
        float mx = v[0];
#pragma unroll
        for (int c = 1; c < F; c++) mx = fmaxf(mx, v[c]);
        float ssum = 0.f;
#pragma unroll
        for (int c = 0; c < F; c++) ssum += __expf(v[c] - mx);
        float lz = mx + __logf(ssum);
#pragma unroll
        for (int c = 0; c < F; c++) g_post[c * NT + n] = v[c] - lz;
    }
}

// ---- LSTM1 input projection as split-K GEMM: grid 96 = t*8+ks, 256 threads ----
#define XPROJ_SMEM ((NG * SLICE + 64 * 128) * 4)   // 32KB posts + 32KB weight chunk

__global__ void __launch_bounds__(256, 1) k_xproj() {
    PDL_TRIGGER();
    extern __shared__ float sm[];
    float* posts = sm;                 // [32][256]
    float* wsm   = sm + NG * SLICE;    // [64][128]

    int tid = threadIdx.x;
    int t = blockIdx.x >> 3, ks = blockIdx.x & 7;
    int jt = tid & 31, bt = tid >> 5;

    PDL_WAIT();   // g_post ready

    const float* src = g_post + t * NT + ks * SLICE;
#pragma unroll
    for (int k = 0; k < NG * SLICE / 256; k++) {
        int idx = k * 256 + tid;
        int b = idx >> 8, n = idx & 255;
        posts[idx] = src[b * NN + n];
    }

    float acc[4][4];
#pragma unroll
    for (int bi = 0; bi < 4; bi++)
#pragma unroll
        for (int ji = 0; ji < 4; ji++) acc[bi][ji] = 0.f;

    for (int c = 0; c < 4; c++) {
        __syncthreads();
        const float* wsrc = g_wT1 + (ks * SLICE + c * 64) * 128;
#pragma unroll
        for (int k = 0; k < 32; k++) wsm[k * 256 + tid] = wsrc[k * 256 + tid];
        __syncthreads();

        const float* prow = posts + c * 64;
#pragma unroll 4
        for (int n = 0; n < 64; n++) {
            float4 w4 = *reinterpret_cast<const float4*>(&wsm[n * 128 + jt * 4]);
            float p0 = prow[(bt * 4 + 0) * SLICE + n];
            float p1 = prow[(bt * 4 + 1) * SLICE + n];
            float p2 = prow[(bt * 4 + 2) * SLICE + n];
            float p3 = prow[(bt * 4 + 3) * SLICE + n];
            acc[0][0] += p0 * w4.x; acc[0][1] += p0 * w4.y; acc[0][2] += p0 * w4.z; acc[0][3] += p0 * w4.w;
            acc[1][0] += p1 * w4.x; acc[1][1] += p1 * w4.y; acc[1][2] += p1 * w4.z; acc[1][3] += p1 * w4.w;
            acc[2][0] += p2 * w4.x; acc[2][1] += p2 * w4.y; acc[2][2] += p2 * w4.z; acc[2][3] += p2 * w4.w;
            acc[3][0] += p3 * w4.x; acc[3][1] += p3 * w4.y; acc[3][2] += p3 * w4.z; acc[3][3] += p3 * w4.w;
        }
    }

    float* dst = g_part + ((t * KS + ks) * NG) * 128;
#pragma unroll
    for (int bi = 0; bi < 4; bi++) {
        float4 v = make_float4(acc[bi][0], acc[bi][1], acc[bi][2], acc[bi][3]);
        *reinterpret_cast<float4*>(&dst[(bt * 4 + bi) * 128 + jt * 4]) = v;
    }
}

// -------- fused LSTM1 recurrence (+split-K reduce) + LSTM2 (clusters of 2) --------
// weight staging happens PRE-WAIT (inputs only) and overlaps k_xproj via PDL.
#define LSTM2_SMEM (256 * 129 * 4)

__global__ void __cluster_dims__(2, 1, 1) __launch_bounds__(256, 1)
k_lstm12(const float* __restrict__ whh1, const float* __restrict__ whh2,
         const float* __restrict__ wih2, const float* __restrict__ bih2,
         const float* __restrict__ bhh2, const float* __restrict__ bih1,
         const float* __restrict__ bhh1) {
    PDL_TRIGGER();
    extern __shared__ float wsm[];                  // [256 rows][129] padded
    __shared__ __align__(16) float h2buf[2][128];
    __shared__ float gs[256];
    __shared__ __align__(16) float xs12[F * 32];
    __shared__ __align__(16) float h1s[32];

    int tid = threadIdx.x;
    int b = blockIdx.x >> 1;
    unsigned r;
    asm("mov.u32 %0, %%cluster_ctarank;" : "=r"(r));

    int gt = tid >> 6, l = tid & 63;
    int jglob = gt * 128 + (int)r * 64 + l;

    for (int idx = tid; idx < 256 * 128; idx += 256) {
        int jl = idx >> 7, k = idx & 127;
        int jg2 = (jl >> 6) * 128 + (int)r * 64 + (jl & 63);
        wsm[jl * 129 + k] = whh2[jg2 * 128 + k];
    }
    float wi[32];
    {
        const float4* wr = reinterpret_cast<const float4*>(wih2 + jglob * 32);
#pragma unroll
        for (int q = 0; q < 8; q++) {
            float4 v = wr[q];
            wi[4 * q] = v.x; wi[4 * q + 1] = v.y; wi[4 * q + 2] = v.z; wi[4 * q + 3] = v.w;
        }
    }
    float bb = bih2[jglob] + bhh2[jglob];
    float c2_reg = 0.f;
    if (tid < 128) h2buf[0][tid] = 0.f;
    if (tid < 32) h1s[tid] = 0.f;

    unsigned peer_h2, peer_xs;
    {
        unsigned a = (unsigned)__cvta_generic_to_shared(&h2buf[0][0]);
        asm("mapa.shared::cluster.u32 %0, %1, %2;" : "=r"(peer_h2) : "r"(a), "r"(r ^ 1u));
        unsigned ax = (unsigned)__cvta_generic_to_shared(&xs12[0]);
        asm("mapa.shared::cluster.u32 %0, %1, %2;" : "=r"(peer_xs) : "r"(ax), "r"(r ^ 1u));
    }

    // LSTM1 weights (inputs) pre-wait as well
    float w1reg[32];
    float b1 = 0.f;
    if (r == 0 && tid < 128) {
        const float4* wr = reinterpret_cast<const float4*>(whh1 + tid * 32);
#pragma unroll
        for (int q = 0; q < 8; q++) {
            float4 v = wr[q];
            w1reg[4 * q] = v.x; w1reg[4 * q + 1] = v.y;
            w1reg[4 * q + 2] = v.z; w1reg[4 * q + 3] = v.w;
        }
        b1 = bih1[tid] + bhh1[tid];
    }

    PDL_WAIT();   // g_part ready

    if (r == 0) {
        float c1_reg = 0.f;
        __syncthreads();
        for (int t = 0; t < F; t++) {
            if (tid < 128) {
                const float* pp = g_part + (t * KS) * (NG * 128) + b * 128 + tid;
                float v = b1;
#pragma unroll
                for (int ks = 0; ks < KS; ks++) v += pp[ks * (NG * 128)];
                const float4* hv = reinterpret_cast<const float4*>(h1s);
#pragma unroll
                for (int q = 0; q < 8; q++) {
                    float4 h4 = hv[q];
                    v += h4.x * w1reg[4 * q] + h4.y * w1reg[4 * q + 1]
                       + h4.z * w1reg[4 * q + 2] + h4.w * w1reg[4 * q + 3];
                }
                gs[tid] = v;
            }
            __syncthreads();
            if (tid < 32) {
                float ig = gs[tid], fg = gs[32 + tid], gg = gs[64 + tid], og = gs[96 + tid];
                float cc = sigf(fg) * c1_reg + sigf(ig) * tanhf(gg);
                c1_reg = cc;
                float hh = sigf(og) * tanhf(cc);
                h1s[tid] = hh;
                xs12[t * 32 + tid] = hh;
            }
            __syncthreads();
        }
        for (int idx = tid; idx < F * 32; idx += 256)
            asm volatile("st.shared::cluster.f32 [%0], %1;"
                         :: "r"(peer_xs + (unsigned)(idx * 4)), "f"(xs12[idx]) : "memory");
    } else {
        __syncthreads();
    }
    asm volatile("barrier.cluster.arrive.aligned;" ::: "memory");
    asm volatile("barrier.cluster.wait.aligned;" ::: "memory");

    const float* wrow = &wsm[tid * 129];
    for (int t = 0; t < F; t++) {
        int cur = t & 1, nxt = cur ^ 1;
        float v = bb;
        const float4* xv = reinterpret_cast<const float4*>(&xs12[t * 32]);
#pragma unroll
        for (int q = 0; q < 8; q++) {
            float4 x4 = xv[q];
            v += x4.x * wi[4 * q] + x4.y * wi[4 * q + 1] + x4.z * wi[4 * q + 2] + x4.w * wi[4 * q + 3];
        }
        const float4* hv = reinterpret_cast<const float4*>(h2buf[cur]);
#pragma unroll
        for (int kk = 0; kk < 32; kk++) {
            float4 h4 = hv[kk];
            v += h4.x * wrow[4 * kk] + h4.y * wrow[4 * kk + 1]
               + h4.z * wrow[4 * kk + 2] + h4.w * wrow[4 * kk + 3];
        }
        gs[tid] = v;
        __syncthreads();
        if (tid < 64) {
            float ig = gs[tid], fg = gs[64 + tid], gg = gs[128 + tid], og = gs[192 + tid];
            float cc = sigf(fg) * c2_reg + sigf(ig) * tanhf(gg);
            c2_reg = cc;
            float hh = sigf(og) * tanhf(cc);
            int jc = (int)r * 64 + tid;
            h2buf[nxt][jc] = hh;
            asm volatile("st.shared::cluster.f32 [%0], %1;"
                         :: "r"(peer_h2 + (unsigned)((nxt * 128 + jc) * 4)), "f"(hh) : "memory");
            if (t >= 3) g_hs2[t * (NG * 128) + b * 128 + jc] = hh;
        }
        asm volatile("barrier.cluster.arrive.aligned;" ::: "memory");
        asm volatile("barrier.cluster.wait.aligned;" ::: "memory");
    }
}

// ---------------- final linear for last 9 timesteps ----------------
__global__ void k_final(const float* __restrict__ linw, const float* __restrict__ linb,
                        float* __restrict__ out) {
    PDL_WAIT();
    int b = blockIdx.x >> 4;
    int c0 = (blockIdx.x & 15) * 128;
    __shared__ __align__(16) float sh[OUTC * 128];
    for (int i = threadIdx.x; i < OUTC * 128; i += blockDim.x) {
        int k = i >> 7, j = i & 127;
        sh[i] = g_hs2[(3 + k) * (NG * 128) + b * 128 + j];
    }
    __syncthreads();
    int warp = threadIdx.x >> 5, lane = threadIdx.x & 31;
    for (int idx = 0; idx < 16; idx++) {
        int n = c0 + warp * 16 + idx;
        float4 w4 = reinterpret_cast<const float4*>(linw + n * 128)[lane];
        float acc[OUTC];
#pragma unroll
        for (int k = 0; k < OUTC; k++) {
            float4 h4 = *reinterpret_cast<float4*>(&sh[k * 128 + lane * 4]);
            acc[k] = w4.x * h4.x + w4.y * h4.y + w4.z * h4.z + w4.w * h4.w;
        }
#pragma unroll
        for (int s = 16; s > 0; s >>= 1)
#pragma unroll
            for (int k = 0; k < OUTC; k++) acc[k] += __shfl_xor_sync(0xffffffffu, acc[k], s);
        if (lane == 0) {
            float lb = linb[n];
            float* o = out + (size_t)(b * NN + n) * OUTC;
#pragma unroll
            for (int k = 0; k < OUTC; k++) o[k] = acc[k] + lb;
        }
    }
}

// ---------------- launch (all PDL-chained) ----------------
static void launch_pdl(const void* fn, dim3 grid, dim3 block, size_t smem, void** args) {
    cudaLaunchConfig_t cfg = {};
    cfg.gridDim = grid;
    cfg.blockDim = block;
    cfg.dynamicSmemBytes = smem;
    cfg.stream = 0;
    cudaLaunchAttribute attr[1];
    attr[0].id = cudaLaunchAttributeProgrammaticStreamSerialization;
    attr[0].val.programmaticStreamSerializationAllowed = 1;
    cfg.attrs = attr;
    cfg.numAttrs = 1;
    cudaLaunchKernelExC(&cfg, fn, args);
}

extern "C" void kernel_launch(void* const* d_in, const int* in_sizes, int n_in,
                              void* d_out, int out_size) {
    const float* x     = (const float*)d_in[0];
    const int*   ei    = (const int*)d_in[1];     // int32: JAX x64 disabled
    const float* Wg    = (const float*)d_in[2];
    const float* a_src = (const float*)d_in[3];
    const float* a_dst = (const float*)d_in[4];
    const float* gbias = (const float*)d_in[5];
    const float* gamma = (const float*)d_in[6];
    const float* beta  = (const float*)d_in[7];
    const float* mean  = (const float*)d_in[8];
    const float* var   = (const float*)d_in[9];
    const float* wih1  = (const float*)d_in[10];
    const float* whh1  = (const float*)d_in[11];
    const float* bih1  = (const float*)d_in[12];
    const float* bhh1  = (const float*)d_in[13];
    const float* wih2  = (const float*)d_in[14];
    const float* whh2  = (const float*)d_in[15];
    const float* bih2  = (const float*)d_in[16];
    const float* bhh2  = (const float*)d_in[17];
    const float* linw  = (const float*)d_in[18];
    const float* linb  = (const float*)d_in[19];
    float* out = (float*)d_out;

    cudaFuncSetAttribute(k_xproj, cudaFuncAttributeMaxDynamicSharedMemorySize, XPROJ_SMEM);
    cudaFuncSetAttribute(k_lstm12, cudaFuncAttributeMaxDynamicSharedMemorySize, LSTM2_SMEM);

    { void* a[] = {(void*)&x, (void*)&Wg, (void*)&a_src, (void*)&a_dst, (void*)&ei};
      launch_pdl((const void*)k_prep, dim3(NT * NHEADS / 256), dim3(256), 0, a); }
    { void* a[] = {(void*)&wih1};
      launch_pdl((const void*)k_scan1, dim3(64), dim3(1024), 0, a); }
    { launch_pdl((const void*)k_scan3, dim3(64), dim3(1024), 0, nullptr); }
    { void* a[] = {(void*)&ei};
      launch_pdl((const void*)k_scatter, dim3(NE / 4 / 256), dim3(256), 0, a); }
    { void* a[] = {(void*)&gbias, (void*)&gamma, (void*)&beta, (void*)&mean, (void*)&var};
      launch_pdl((const void*)k_gat, dim3(NT * NHEADS / 256), dim3(256), 0, a); }
    { launch_pdl((const void*)k_xproj, dim3(F * KS), dim3(256), XPROJ_SMEM, nullptr); }
    { void* a[] = {(void*)&whh1, (void*)&whh2, (void*)&wih2, (void*)&bih2, (void*)&bhh2,
                   (void*)&bih1, (void*)&bhh1};
      launch_pdl((const void*)k_lstm12, dim3(NG * 2), dim3(256), LSTM2_SMEM, a); }
    { void* a[] = {(void*)&linw, (void*)&linb, (void*)&out};
      launch_pdl((const void*)k_final, dim3(NG * 16), dim3(256), 0, a); }
}

// round 11
// speedup vs baseline: 1.0290x; 1.0290x over previous
#include <cuda_runtime.h>
#include <cuda_fp16.h>

#define NG 32
#define NN 2048
#define NT 65536           // NG*NN
#define NE 1048576
#define NHEADS 8
#define F 12               // GAT_OUT
#define FH 96              // NHEADS*F
#define OUTC 9
#define KS 8               // K-slices for xproj split-K
#define SLICE 256          // n per slice (KS*SLICE = NN)

// ---------------- scratch (static device memory only) ----------------
__device__ __align__(16) uint4 g_rec[NT * NHEADS * 2];   // {asrc f32 | 12 x f16 | pad} per (n,h)
__device__ float g_adst[NT * NHEADS];
__device__ int   g_deg[NT];            // BSS-zero; re-zeroed by k_scan each run
__device__ int   g_off[NT + 1];
__device__ int   g_cur[NT];
__device__ int   g_bsum[64];
__device__ unsigned g_tix;             // monotonic grid-barrier ticket (BSS-zero)
__device__ int   g_csr[NE];
__device__ __align__(16) float g_post[F * NT];             // channel-major [t][gn]
__device__ __align__(16) float g_wT1[NN * 128];            // w_ih1^T [n][j]
__device__ __align__(16) float g_part[F * KS * NG * 128];  // split-K partials [t][ks][b][j]
__device__ __align__(16) float g_hs2[F * NG * 128];

__device__ __forceinline__ float lrelu(float v) { return v > 0.f ? v : 0.2f * v; }
__device__ __forceinline__ float sigf(float v) { return 1.0f / (1.0f + __expf(-v)); }

// ---- prep: xp = x@W + logits, pack records, edge histogram ----
__global__ void k_prep(const float* __restrict__ x, const float* __restrict__ W,
                       const float* __restrict__ av_s, const float* __restrict__ av_d,
                       const int* __restrict__ ei) {
    __shared__ float Ws[F * FH];
    __shared__ float as_s[FH], ad_s[FH];
    for (int i = threadIdx.x; i < F * FH; i += blockDim.x) Ws[i] = W[i];
    for (int i = threadIdx.x; i < FH; i += blockDim.x) { as_s[i] = av_s[i]; ad_s[i] = av_d[i]; }
    __syncthreads();

    int gid = blockIdx.x * blockDim.x + threadIdx.x;   // 0 .. 524287 = n*8+h

    atomicAdd(&g_deg[ei[NE + gid]], 1);
    atomicAdd(&g_deg[ei[NE + gid + NT * NHEADS]], 1);

    int n = gid >> 3, h = gid & 7;
    const float4* xv = reinterpret_cast<const float4*>(x + n * F);
    float4 v0 = xv[0], v1 = xv[1], v2 = xv[2];
    float xr[F] = {v0.x, v0.y, v0.z, v0.w, v1.x, v1.y, v1.z, v1.w, v2.x, v2.y, v2.z, v2.w};

    float o[F];
    float sa = 0.f, sd = 0.f;
#pragma unroll
    for (int c = 0; c < F; c++) {
        float s = 0.f;
#pragma unroll
        for (int k = 0; k < F; k++) s += xr[k] * Ws[k * FH + h * F + c];
        o[c] = s;
        sa += s * as_s[h * F + c];
        sd += s * ad_s[h * F + c];
    }
    uint4 r0, r1;
    r0.x = __float_as_uint(sa);
    __half2 p;
    p = __floats2half2_rn(o[0], o[1]);   r0.y = *reinterpret_cast<unsigned*>(&p);
    p = __floats2half2_rn(o[2], o[3]);   r0.z = *reinterpret_cast<unsigned*>(&p);
    p = __floats2half2_rn(o[4], o[5]);   r0.w = *reinterpret_cast<unsigned*>(&p);
    p = __floats2half2_rn(o[6], o[7]);   r1.x = *reinterpret_cast<unsigned*>(&p);
    p = __floats2half2_rn(o[8], o[9]);   r1.y = *reinterpret_cast<unsigned*>(&p);
    p = __floats2half2_rn(o[10], o[11]); r1.z = *reinterpret_cast<unsigned*>(&p);
    r1.w = 0u;
    g_rec[gid * 2]     = r0;
    g_rec[gid * 2 + 1] = r1;
    g_adst[gid] = sd;
}

// ---- software grid barrier for the fixed 64-block kernel (monotonic ticket) ----
__device__ __forceinline__ void gridbar64() {
    __syncthreads();
    if (threadIdx.x == 0) {
        __threadfence();
        unsigned t = atomicAdd(&g_tix, 1u);
        unsigned target = (t / 64u + 1u) * 64u;
        while (*(volatile unsigned*)&g_tix < target) { }
        __threadfence();
    }
    __syncthreads();
}

// ---- scan: (prologue) coalesced w_ih1 transpose, then full degree scan (fused 2-level) ----
__global__ void __launch_bounds__(1024, 1) k_scan(const float* __restrict__ w1) {
    __shared__ float ts[32][33];
    int tid = threadIdx.x;
    int r = tid >> 5, c = tid & 31;
    // transpose 128x2048 -> 2048x128 in 32x32 tiles; 256 tiles, 4 per block
#pragma unroll
    for (int q = 0; q < 4; q++) {
        int t = blockIdx.x * 4 + q;
        int j0 = (t >> 6) * 32, n0 = (t & 63) * 32;
        ts[r][c] = w1[(j0 + r) * NN + n0 + c];
        __syncthreads();
        g_wT1[(n0 + r) * 128 + j0 + c] = ts[c][r];
        __syncthreads();
    }

    // phase 1: block-local exclusive scan of degrees
    int g = blockIdx.x * 1024 + tid;
    int lane = tid & 31, wid = tid >> 5;
    int v = g_deg[g];
    int incl = v;
#pragma unroll
    for (int off = 1; off < 32; off <<= 1) {
        int t = __shfl_up_sync(0xffffffffu, incl, off);
        if (lane >= off) incl += t;
    }
    __shared__ int wsum[32];
    if (lane == 31) wsum[wid] = incl;
    __syncthreads();
    if (wid == 0) {
        int s = wsum[lane];
        int si = s;
#pragma unroll
        for (int off = 1; off < 32; off <<= 1) {
            int t = __shfl_up_sync(0xffffffffu, si, off);
            if (lane >= off) si += t;
        }
        wsum[lane] = si - s;
    }
    __syncthreads();
    incl += wsum[wid];
    int loc_ex = incl - v;
    if (tid == 1023) g_bsum[blockIdx.x] = incl;

    gridbar64();

    // phase 2: apply block prefix, produce off/cur, re-zero deg
    __shared__ int tmp[64];
    __shared__ int pre;
    if (tid < 64) tmp[tid] = g_bsum[tid];
    __syncthreads();
    if (tid == 0) {
        int s = 0;
        int nb = blockIdx.x;
        for (int i = 0; i < nb; i++) s += tmp[i];
        pre = s;
    }
    __syncthreads();
    int o = loc_ex + pre;
    g_off[g] = o;
    g_cur[g] = o;
    g_deg[g] = 0;
    if (g == 0) g_off[NT] = NE;
}

// ---- scatter: 1 edge per thread, full grid (measured-best form) ----
__global__ void k_scatter(const int* __restrict__ ei) {
    int e = blockIdx.x * blockDim.x + threadIdx.x;
    if (e < NE) {
        int d = ei[NE + e];
        int s = ei[e];
        int pos = atomicAdd(&g_cur[d], 1);
        g_csr[pos] = s;
    }
}

// ---- GAT aggregation: thread-per-(n,h), 4-edge batches ----
__global__ void __launch_bounds__(256) k_gat(
        const float* __restrict__ bias, const float* __restrict__ gamma,
        const float* __restrict__ beta, const float* __restrict__ mean,
        const float* __restrict__ var) {
    __shared__ float sb[F], sg[F], sbe[F], smn[F], svr[F];
    if (threadIdx.x < F) {
        sb[threadIdx.x]  = bias[threadIdx.x];
        sg[threadIdx.x]  = gamma[threadIdx.x];
        sbe[threadIdx.x] = beta[threadIdx.x];
        smn[threadIdx.x] = mean[threadIdx.x];
        svr[threadIdx.x] = var[threadIdx.x];
    }
    __syncthreads();

    int gid = blockIdx.x * blockDim.x + threadIdx.x;   // n*8 + h
    int n = gid >> 3, h = gid & 7;
    float adn = g_adst[gid];
    int st = g_off[n], en = g_off[n + 1];

    float denom = 0.f;
    float acc[F];
#pragma unroll
    for (int c = 0; c < F; c++) acc[c] = 0.f;

#define ACC2(r0, r1)                                                           \
    {                                                                          \
        float w = __expf(lrelu(__uint_as_float(r0.x) + adn));                  \
        denom += w;                                                            \
        __half2 hp; float2 f2;                                                 \
        hp = *reinterpret_cast<__half2*>(&r0.y); f2 = __half22float2(hp);      \
        acc[0] += w * f2.x; acc[1] += w * f2.y;                                \
        hp = *reinterpret_cast<__half2*>(&r0.z); f2 = __half22float2(hp);      \
        acc[2] += w * f2.x; acc[3] += w * f2.y;                                \
        hp = *reinterpret_cast<__half2*>(&r0.w); f2 = __half22float2(hp);      \
        acc[4] += w * f2.x; acc[5] += w * f2.y;                                \
        hp = *reinterpret_cast<__half2*>(&r1.x); f2 = __half22float2(hp);      \
        acc[6] += w * f2.x; acc[7] += w * f2.y;                                \
        hp = *reinterpret_cast<__half2*>(&r1.y); f2 = __half22float2(hp);      \
        acc[8] += w * f2.x; acc[9] += w * f2.y;                                \
        hp = *reinterpret_cast<__half2*>(&r1.z); f2 = __half22float2(hp);      \
        acc[10] += w * f2.x; acc[11] += w * f2.y;                              \
    }

    {
        uint4 a0 = g_rec[(unsigned)gid * 2u], a1 = g_rec[(unsigned)gid * 2u + 1u];
        ACC2(a0, a1);
    }
    int i = st;
    for (; i + 4 <= en; i += 4) {
        int s0 = g_csr[i], s1 = g_csr[i + 1], s2 = g_csr[i + 2], s3 = g_csr[i + 3];
        const uint4* p0 = &g_rec[(unsigned)(s0 * NHEADS + h) * 2u];
        const uint4* p1 = &g_rec[(unsigned)(s1 * NHEADS + h) * 2u];
        const uint4* p2 = &g_rec[(unsigned)(s2 * NHEADS + h) * 2u];
        const uint4* p3 = &g_rec[(unsigned)(s3 * NHEADS + h) * 2u];
        uint4 a0 = p0[0], a1 = p0[1];
        uint4 b0 = p1[0], b1 = p1[1];
        uint4 c0 = p2[0], c1 = p2[1];
        uint4 d0 = p3[0], d1 = p3[1];
        ACC2(a0, a1); ACC2(b0, b1); ACC2(c0, c1); ACC2(d0, d1);
    }
    for (; i < en; i++) {
        int s = g_csr[i];
        const uint4* rp = &g_rec[(unsigned)(s * NHEADS + h) * 2u];
        uint4 a0 = rp[0], a1 = rp[1];
        ACC2(a0, a1);
    }
#undef ACC2

    float inv = 1.f / (denom + 1e-16f);
#pragma unroll
    for (int c = 0; c < F; c++) acc[c] *= inv;

#pragma unroll
    for (int s = 4; s > 0; s >>= 1)
#pragma unroll
        for (int c = 0; c < F; c++) acc[c] += __shfl_xor_sync(0xffffffffu, acc[c], s);

    if (h == 0) {
        float v[F];
#pragma unroll
        for (int c = 0; c < F; c++) {
            float t = acc[c] * 0.125f + sb[c];
            v[c] = (t - smn[c]) * rsqrtf(svr[c] + 1e-5f) * sg[c] + sbe[c];
        }
        float mx = v[0];
#pragma unroll
        for (int c = 1; c < F; c++) mx = fmaxf(mx, v[c]);
        float ssum = 0.f;
#pragma unroll
        for (int c = 0; c < F; c++) ssum += __expf(v[c] - mx);
        float lz = mx + __logf(ssum);
#pragma unroll
        for (int c = 0; c < F; c++) g_post[c * NT + n] = v[c] - lz;
    }
}

// ---- LSTM1 input projection as split-K GEMM: grid 96 = t*8+ks, 256 threads ----
#define XPROJ_SMEM ((NG * SLICE + 64 * 128) * 4)   // 32KB posts + 32KB weight chunk

__global__ void __launch_bounds__(256, 1) k_xproj() {
    extern __shared__ float sm[];
    float* posts = sm;                 // [32][256]
    float* wsm   = sm + NG * SLICE;    // [64][128]

    int tid = threadIdx.x;
    int t = blockIdx.x >> 3, ks = blockIdx.x & 7;
    int jt = tid & 31, bt = tid >> 5;

    const float* src = g_post + t * NT + ks * SLICE;
#pragma unroll
    for (int k = 0; k < NG * SLICE / 256; k++) {
        int idx = k * 256 + tid;
        int b = idx >> 8, n = idx & 255;
        posts[idx] = src[b * NN + n];
    }

    float acc[4][4];
#pragma unroll
    for (int bi = 0; bi < 4; bi++)
#pragma unroll
        for (int ji = 0; ji < 4; ji++) acc[bi][ji] = 0.f;

    for (int c = 0; c < 4; c++) {
        __syncthreads();
        const float* wsrc = g_wT1 + (ks * SLICE + c * 64) * 128;
#pragma unroll
        for (int k = 0; k < 32; k++) wsm[k * 256 + tid] = wsrc[k * 256 + tid];
        __syncthreads();

        const float* prow = posts + c * 64;
#pragma unroll 4
        for (int n = 0; n < 64; n++) {
            float4 w4 = *reinterpret_cast<const float4*>(&wsm[n * 128 + jt * 4]);
            float p0 = prow[(bt * 4 + 0) * SLICE + n];
            float p1 = prow[(bt * 4 + 1) * SLICE + n];
            float p2 = prow[(bt * 4 + 2) * SLICE + n];
            float p3 = prow[(bt * 4 + 3) * SLICE + n];
            acc[0][0] += p0 * w4.x; acc[0][1] += p0 * w4.y; acc[0][2] += p0 * w4.z; acc[0][3] += p0 * w4.w;
            acc[1][0] += p1 * w4.x; acc[1][1] += p1 * w4.y; acc[1][2] += p1 * w4.z; acc[1][3] += p1 * w4.w;
            acc[2][0] += p2 * w4.x; acc[2][1] += p2 * w4.y; acc[2][2] += p2 * w4.z; acc[2][3] += p2 * w4.w;
            acc[3][0] += p3 * w4.x; acc[3][1] += p3 * w4.y; acc[3][2] += p3 * w4.z; acc[3][3] += p3 * w4.w;
        }
    }

    float* dst = g_part + ((t * KS + ks) * NG) * 128;
#pragma unroll
    for (int bi = 0; bi < 4; bi++) {
        float4 v = make_float4(acc[bi][0], acc[bi][1], acc[bi][2], acc[bi][3]);
        *reinterpret_cast<float4*>(&dst[(bt * 4 + bi) * 128 + jt * 4]) = v;
    }
}

// -------- fused LSTM1 recurrence (+split-K reduce) + LSTM2 (clusters of 2) --------
#define LSTM2_SMEM (256 * 129 * 4)

__global__ void __cluster_dims__(2, 1, 1) __launch_bounds__(256, 1)
k_lstm12(const float* __restrict__ whh1, const float* __restrict__ whh2,
         const float* __restrict__ wih2, const float* __restrict__ bih2,
         const float* __restrict__ bhh2, const float* __restrict__ bih1,
         const float* __restrict__ bhh1) {
    extern __shared__ float wsm[];                  // [256 rows][129] padded
    __shared__ __align__(16) float h2buf[2][128];
    __shared__ float gs[256];
    __shared__ __align__(16) float xs12[F * 32];
    __shared__ __align__(16) float h1s[32];

    int tid = threadIdx.x;
    int b = blockIdx.x >> 1;
    unsigned r;
    asm("mov.u32 %0, %%cluster_ctarank;" : "=r"(r));

    int gt = tid >> 6, l = tid & 63;
    int jglob = gt * 128 + (int)r * 64 + l;

    for (int idx = tid; idx < 256 * 128; idx += 256) {
        int jl = idx >> 7, k = idx & 127;
        int jg2 = (jl >> 6) * 128 + (int)r * 64 + (jl & 63);
        wsm[jl * 129 + k] = whh2[jg2 * 128 + k];
    }
    float wi[32];
    {
        const float4* wr = reinterpret_cast<const float4*>(wih2 + jglob * 32);
#pragma unroll
        for (int q = 0; q < 8; q++) {
            float4 v = wr[q];
            wi[4 * q] = v.x; wi[4 * q + 1] = v.y; wi[4 * q + 2] = v.z; wi[4 * q + 3] = v.w;
        }
    }
    float bb = bih2[jglob] + bhh2[jglob];
    float c2_reg = 0.f;
    if (tid < 128) h2buf[0][tid] = 0.f;
    if (tid < 32) h1s[tid] = 0.f;

    unsigned peer_h2, peer_xs;
    {
        unsigned a = (unsigned)__cvta_generic_to_shared(&h2buf[0][0]);
        asm("mapa.shared::cluster.u32 %0, %1, %2;" : "=r"(peer_h2) : "r"(a), "r"(r ^ 1u));
        unsigned ax = (unsigned)__cvta_generic_to_shared(&xs12[0]);
        asm("mapa.shared::cluster.u32 %0, %1, %2;" : "=r"(peer_xs) : "r"(ax), "r"(r ^ 1u));
    }

    if (r == 0) {
        float w1reg[32];
        float b1 = 0.f;
        if (tid < 128) {
            const float4* wr = reinterpret_cast<const float4*>(whh1 + tid * 32);
#pragma unroll
            for (int q = 0; q < 8; q++) {
                float4 v = wr[q];
                w1reg[4 * q] = v.x; w1reg[4 * q + 1] = v.y;
                w1reg[4 * q + 2] = v.z; w1reg[4 * q + 3] = v.w;
            }
            b1 = bih1[tid] + bhh1[tid];
        }
        float c1_reg = 0.f;
        __syncthreads();
        for (int t = 0; t < F; t++) {
            if (tid < 128) {
                const float* pp = g_part + (t * KS) * (NG * 128) + b * 128 + tid;
                float v = b1;
#pragma unroll
                for (int ks = 0; ks < KS; ks++) v += pp[ks * (NG * 128)];
                const float4* hv = reinterpret_cast<const float4*>(h1s);
#pragma unroll
                for (int q = 0; q < 8; q++) {
                    float4 h4 = hv[q];
                    v += h4.x * w1reg[4 * q] + h4.y * w1reg[4 * q + 1]
                       + h4.z * w1reg[4 * q + 2] + h4.w * w1reg[4 * q + 3];
                }
                gs[tid] = v;
            }
            __syncthreads();
            if (tid < 32) {
                float ig = gs[tid], fg = gs[32 + tid], gg = gs[64 + tid], og = gs[96 + tid];
                float cc = sigf(fg) * c1_reg + sigf(ig) * tanhf(gg);
                c1_reg = cc;
                float hh = sigf(og) * tanhf(cc);
                h1s[tid] = hh;
                xs12[t * 32 + tid] = hh;
            }
            __syncthreads();
        }
        for (int idx = tid; idx < F * 32; idx += 256)
            asm volatile("st.shared::cluster.f32 [%0], %1;"
                         :: "r"(peer_xs + (unsigned)(idx * 4)), "f"(xs12[idx]) : "memory");
    } else {
        __syncthreads();
    }
    asm volatile("barrier.cluster.arrive.aligned;" ::: "memory");
    asm volatile("barrier.cluster.wait.aligned;" ::: "memory");

    const float* wrow = &wsm[tid * 129];
    for (int t = 0; t < F; t++) {
        int cur = t & 1, nxt = cur ^ 1;
        float v = bb;
        const float4* xv = reinterpret_cast<const float4*>(&xs12[t * 32]);
#pragma unroll
        for (int q = 0; q < 8; q++) {
            float4 x4 = xv[q];
            v += x4.x * wi[4 * q] + x4.y * wi[4 * q + 1] + x4.z * wi[4 * q + 2] + x4.w * wi[4 * q + 3];
        }
        const float4* hv = reinterpret_cast<const float4*>(h2buf[cur]);
#pragma unroll
        for (int kk = 0; kk < 32; kk++) {
            float4 h4 = hv[kk];
            v += h4.x * wrow[4 * kk] + h4.y * wrow[4 * kk + 1]
               + h4.z * wrow[4 * kk + 2] + h4.w * wrow[4 * kk + 3];
        }
        gs[tid] = v;
        __syncthreads();
        if (tid < 64) {
            float ig = gs[tid], fg = gs[64 + tid], gg = gs[128 + tid], og = gs[192 + tid];
            float cc = sigf(fg) * c2_reg + sigf(ig) * tanhf(gg);
            c2_reg = cc;
            float hh = sigf(og) * tanhf(cc);
            int jc = (int)r * 64 + tid;
            h2buf[nxt][jc] = hh;
            asm volatile("st.shared::cluster.f32 [%0], %1;"
                         :: "r"(peer_h2 + (unsigned)((nxt * 128 + jc) * 4)), "f"(hh) : "memory");
            if (t >= 3) g_hs2[t * (NG * 128) + b * 128 + jc] = hh;
        }
        asm volatile("barrier.cluster.arrive.aligned;" ::: "memory");
        asm volatile("barrier.cluster.wait.aligned;" ::: "memory");
    }
}

// ---------------- final linear for last 9 timesteps ----------------
__global__ void k_final(const float* __restrict__ linw, const float* __restrict__ linb,
                        float* __restrict__ out) {
    int b = blockIdx.x >> 4;
    int c0 = (blockIdx.x & 15) * 128;
    __shared__ __align__(16) float sh[OUTC * 128];
    for (int i = threadIdx.x; i < OUTC * 128; i += blockDim.x) {
        int k = i >> 7, j = i & 127;
        sh[i] = g_hs2[(3 + k) * (NG * 128) + b * 128 + j];
    }
    __syncthreads();
    int warp = threadIdx.x >> 5, lane = threadIdx.x & 31;
    for (int idx = 0; idx < 16; idx++) {
        int n = c0 + warp * 16 + idx;
        float4 w4 = reinterpret_cast<const float4*>(linw + n * 128)[lane];
        float acc[OUTC];
#pragma unroll
        for (int k = 0; k < OUTC; k++) {
            float4 h4 = *reinterpret_cast<float4*>(&sh[k * 128 + lane * 4]);
            acc[k] = w4.x * h4.x + w4.y * h4.y + w4.z * h4.z + w4.w * h4.w;
        }
#pragma unroll
        for (int s = 16; s > 0; s >>= 1)
#pragma unroll
            for (int k = 0; k < OUTC; k++) acc[k] += __shfl_xor_sync(0xffffffffu, acc[k], s);
        if (lane == 0) {
            float lb = linb[n];
            float* o = out + (size_t)(b * NN + n) * OUTC;
#pragma unroll
            for (int k = 0; k < OUTC; k++) o[k] = acc[k] + lb;
        }
    }
}

// ---------------- launch ----------------
extern "C" void kernel_launch(void* const* d_in, const int* in_sizes, int n_in,
                              void* d_out, int out_size) {
    const float* x     = (const float*)d_in[0];
    const int*   ei    = (const int*)d_in[1];     // int32: JAX x64 disabled
    const float* Wg    = (const float*)d_in[2];
    const float* a_src = (const float*)d_in[3];
    const float* a_dst = (const float*)d_in[4];
    const float* gbias = (const float*)d_in[5];
    const float* gamma = (const float*)d_in[6];
    const float* beta  = (const float*)d_in[7];
    const float* mean  = (const float*)d_in[8];
    const float* var   = (const float*)d_in[9];
    const float* wih1  = (const float*)d_in[10];
    const float* whh1  = (const float*)d_in[11];
    const float* bih1  = (const float*)d_in[12];
    const float* bhh1  = (const float*)d_in[13];
    const float* wih2  = (const float*)d_in[14];
    const float* whh2  = (const float*)d_in[15];
    const float* bih2  = (const float*)d_in[16];
    const float* bhh2  = (const float*)d_in[17];
    const float* linw  = (const float*)d_in[18];
    const float* linb  = (const float*)d_in[19];
    float* out = (float*)d_out;

    cudaFuncSetAttribute(k_xproj, cudaFuncAttributeMaxDynamicSharedMemorySize, XPROJ_SMEM);
    cudaFuncSetAttribute(k_lstm12, cudaFuncAttributeMaxDynamicSharedMemorySize, LSTM2_SMEM);

    k_prep<<<NT * NHEADS / 256, 256>>>(x, Wg, a_src, a_dst, ei);
    k_scan<<<64, 1024>>>(wih1);
    k_scatter<<<NE / 256, 256>>>(ei);
    k_gat<<<NT * NHEADS / 256, 256>>>(gbias, gamma, beta, mean, var);
    k_xproj<<<F * KS, 256, XPROJ_SMEM>>>();
    k_lstm12<<<NG * 2, 256, LSTM2_SMEM>>>(whh1, whh2, wih2, bih2, bhh2, bih1, bhh1);
    k_final<<<NG * 16, 256>>>(linw, linb, out);
}